// round 2
// baseline (speedup 1.0000x reference)
#include <cuda_runtime.h>
#include <math.h>

#define NB 4
#define NS 4096
#define ND 1024
#define NM (NB*NS)          // 16384 rows
#define NWIN 384            // key window per 128-query tile: [i0-128, i0+255]
#define APR 128
#define LN_EPS 1e-6f

// Scratch (static device memory; no allocations anywhere).
__device__ float g_Q[(size_t)NM * ND];   // Q, later attn-out c, later k1-out h
__device__ float g_K[(size_t)NM * ND];   // K, later Wo-out + residual
__device__ float g_V[(size_t)NM * ND];   // V, later LN1 output y
__device__ float g_E[(size_t)NM * NWIN]; // banded scores -> alpha (in place)

// ---------------------------------------------------------------------------
// 128x128x8 double-buffered TN SGEMM: C[m,n] = sum_k A[m,k] * W[n,k]
// EPI: 0 = plain, 1 = bias+relu, 2 = +residual
// ---------------------------------------------------------------------------
template<int EPI>
__global__ void __launch_bounds__(256)
sgemm_tn(const float* __restrict__ A, const float* __restrict__ W,
         const float* __restrict__ bias, const float* __restrict__ res,
         float* __restrict__ C)
{
    __shared__ float As[2][8][128];
    __shared__ float Bs[2][8][128];
    const int m0 = blockIdx.y << 7;
    const int n0 = blockIdx.x << 7;
    const int tid = threadIdx.x;
    const int tx = tid & 15;
    const int ty = tid >> 4;
    const int lr = tid >> 1;          // 0..127 row within tile
    const int lc = (tid & 1) << 2;    // 0 or 4 (k offset)

    const float* Ap = A + (size_t)(m0 + lr) * ND + lc;
    const float* Wp = W + (size_t)(n0 + lr) * ND + lc;

    float acc[8][8];
#pragma unroll
    for (int i = 0; i < 8; i++)
#pragma unroll
        for (int j = 0; j < 8; j++) acc[i][j] = 0.f;

    float4 apre = *(const float4*)Ap;
    float4 bpre = *(const float4*)Wp;
    As[0][lc+0][lr] = apre.x; As[0][lc+1][lr] = apre.y;
    As[0][lc+2][lr] = apre.z; As[0][lc+3][lr] = apre.w;
    Bs[0][lc+0][lr] = bpre.x; Bs[0][lc+1][lr] = bpre.y;
    Bs[0][lc+2][lr] = bpre.z; Bs[0][lc+3][lr] = bpre.w;
    __syncthreads();

    int buf = 0;
    const int NT = ND / 8;
    for (int t = 0; t < NT; t++) {
        if (t + 1 < NT) {
            apre = *(const float4*)(Ap + (t + 1) * 8);
            bpre = *(const float4*)(Wp + (t + 1) * 8);
        }
#pragma unroll
        for (int kk = 0; kk < 8; kk++) {
            float4 a0 = *(const float4*)&As[buf][kk][ty*8];
            float4 a1 = *(const float4*)&As[buf][kk][ty*8+4];
            float4 b0 = *(const float4*)&Bs[buf][kk][tx*8];
            float4 b1 = *(const float4*)&Bs[buf][kk][tx*8+4];
            float av[8] = {a0.x,a0.y,a0.z,a0.w,a1.x,a1.y,a1.z,a1.w};
            float bv[8] = {b0.x,b0.y,b0.z,b0.w,b1.x,b1.y,b1.z,b1.w};
#pragma unroll
            for (int i = 0; i < 8; i++)
#pragma unroll
                for (int j = 0; j < 8; j++)
                    acc[i][j] = fmaf(av[i], bv[j], acc[i][j]);
        }
        if (t + 1 < NT) {
            const int nb = buf ^ 1;
            As[nb][lc+0][lr] = apre.x; As[nb][lc+1][lr] = apre.y;
            As[nb][lc+2][lr] = apre.z; As[nb][lc+3][lr] = apre.w;
            Bs[nb][lc+0][lr] = bpre.x; Bs[nb][lc+1][lr] = bpre.y;
            Bs[nb][lc+2][lr] = bpre.z; Bs[nb][lc+3][lr] = bpre.w;
            __syncthreads();
            buf = nb;
        }
    }

    float4 bias0 = make_float4(0,0,0,0), bias1 = make_float4(0,0,0,0);
    if (EPI == 1) {
        bias0 = *(const float4*)(bias + n0 + tx*8);
        bias1 = *(const float4*)(bias + n0 + tx*8 + 4);
    }
#pragma unroll
    for (int i = 0; i < 8; i++) {
        const size_t off = (size_t)(m0 + ty*8 + i) * ND + n0 + tx*8;
        float4 o0 = make_float4(acc[i][0], acc[i][1], acc[i][2], acc[i][3]);
        float4 o1 = make_float4(acc[i][4], acc[i][5], acc[i][6], acc[i][7]);
        if (EPI == 1) {
            o0.x = fmaxf(o0.x + bias0.x, 0.f); o0.y = fmaxf(o0.y + bias0.y, 0.f);
            o0.z = fmaxf(o0.z + bias0.z, 0.f); o0.w = fmaxf(o0.w + bias0.w, 0.f);
            o1.x = fmaxf(o1.x + bias1.x, 0.f); o1.y = fmaxf(o1.y + bias1.y, 0.f);
            o1.z = fmaxf(o1.z + bias1.z, 0.f); o1.w = fmaxf(o1.w + bias1.w, 0.f);
        }
        if (EPI == 2) {
            float4 r0 = *(const float4*)(res + off);
            float4 r1 = *(const float4*)(res + off + 4);
            o0.x += r0.x; o0.y += r0.y; o0.z += r0.z; o0.w += r0.w;
            o1.x += r1.x; o1.y += r1.y; o1.z += r1.z; o1.w += r1.w;
        }
        *(float4*)(C + off)     = o0;
        *(float4*)(C + off + 4) = o1;
    }
}

// ---------------------------------------------------------------------------
// Banded scores: E[(b,i), kt*128 + jj] = (Q_i . K_j) / 32,  j = i0-128+kt*128+jj
// One block per (kt, qtile, b) computes a 128x128 tile; K-dim = 1024.
// ---------------------------------------------------------------------------
__global__ void __launch_bounds__(256)
scores_kernel(const float* __restrict__ Q, const float* __restrict__ Km,
              float* __restrict__ E)
{
    __shared__ float As[2][8][128];
    __shared__ float Bs[2][8][128];
    const int b  = blockIdx.z;
    const int i0 = blockIdx.y << 7;
    const int kt = blockIdx.x;
    const int tid = threadIdx.x;
    const int tx = tid & 15;
    const int ty = tid >> 4;
    const int lr = tid >> 1;
    const int lc = (tid & 1) << 2;

    const float* Ap = Q + (size_t)(b * NS + i0 + lr) * ND + lc;
    const int jrow = i0 - APR + kt * 128 + lr;
    const bool jok = (jrow >= 0) && (jrow < NS);
    const float* Wp = jok ? (Km + (size_t)(b * NS + jrow) * ND + lc) : Km;

    float acc[8][8];
#pragma unroll
    for (int i = 0; i < 8; i++)
#pragma unroll
        for (int j = 0; j < 8; j++) acc[i][j] = 0.f;

    float4 apre = *(const float4*)Ap;
    float4 bpre = make_float4(0,0,0,0);
    if (jok) bpre = *(const float4*)Wp;
    As[0][lc+0][lr] = apre.x; As[0][lc+1][lr] = apre.y;
    As[0][lc+2][lr] = apre.z; As[0][lc+3][lr] = apre.w;
    Bs[0][lc+0][lr] = bpre.x; Bs[0][lc+1][lr] = bpre.y;
    Bs[0][lc+2][lr] = bpre.z; Bs[0][lc+3][lr] = bpre.w;
    __syncthreads();

    int buf = 0;
    const int NT = ND / 8;
    for (int t = 0; t < NT; t++) {
        if (t + 1 < NT) {
            apre = *(const float4*)(Ap + (t + 1) * 8);
            bpre = make_float4(0,0,0,0);
            if (jok) bpre = *(const float4*)(Wp + (t + 1) * 8);
        }
#pragma unroll
        for (int kk = 0; kk < 8; kk++) {
            float4 a0 = *(const float4*)&As[buf][kk][ty*8];
            float4 a1 = *(const float4*)&As[buf][kk][ty*8+4];
            float4 b0 = *(const float4*)&Bs[buf][kk][tx*8];
            float4 b1 = *(const float4*)&Bs[buf][kk][tx*8+4];
            float av[8] = {a0.x,a0.y,a0.z,a0.w,a1.x,a1.y,a1.z,a1.w};
            float bv[8] = {b0.x,b0.y,b0.z,b0.w,b1.x,b1.y,b1.z,b1.w};
#pragma unroll
            for (int i = 0; i < 8; i++)
#pragma unroll
                for (int j = 0; j < 8; j++)
                    acc[i][j] = fmaf(av[i], bv[j], acc[i][j]);
        }
        if (t + 1 < NT) {
            const int nb = buf ^ 1;
            As[nb][lc+0][lr] = apre.x; As[nb][lc+1][lr] = apre.y;
            As[nb][lc+2][lr] = apre.z; As[nb][lc+3][lr] = apre.w;
            Bs[nb][lc+0][lr] = bpre.x; Bs[nb][lc+1][lr] = bpre.y;
            Bs[nb][lc+2][lr] = bpre.z; Bs[nb][lc+3][lr] = bpre.w;
            __syncthreads();
            buf = nb;
        }
    }

    const float scale = 0.03125f;  // 1/sqrt(1024)
#pragma unroll
    for (int i = 0; i < 8; i++) {
        const size_t off = (size_t)(b * NS + i0 + ty*8 + i) * NWIN + kt*128 + tx*8;
        float4 o0 = make_float4(acc[i][0]*scale, acc[i][1]*scale, acc[i][2]*scale, acc[i][3]*scale);
        float4 o1 = make_float4(acc[i][4]*scale, acc[i][5]*scale, acc[i][6]*scale, acc[i][7]*scale);
        *(float4*)(E + off)     = o0;
        *(float4*)(E + off + 4) = o1;
    }
}

// ---------------------------------------------------------------------------
// Banded softmax over the 384-entry window; one warp per query row, in place.
// Mask: j in [0,S), |j-i|<=128, j!=i, and e!=0 (reference's scope==0 quirk).
// ---------------------------------------------------------------------------
__global__ void __launch_bounds__(256)
softmax_kernel(float* __restrict__ E)
{
    const int warp = threadIdx.x >> 5;
    const int lane = threadIdx.x & 31;
    const int r = blockIdx.x * 8 + warp;       // 0..NM-1
    const int i = r & (NS - 1);
    const int i0 = i & ~127;
    const int jbase = i0 - APR;
    float* row = E + (size_t)r * NWIN;

    float vals[12];
    float mx = -INFINITY;
#pragma unroll
    for (int u = 0; u < 12; u++) {
        const int l = lane + 32 * u;
        const int j = jbase + l;
        const float e = row[l];
        const bool ok = (j >= 0) && (j < NS) && (j >= i - APR) && (j <= i + APR)
                        && (j != i) && (e != 0.0f);
        vals[u] = ok ? e : -INFINITY;
        mx = fmaxf(mx, vals[u]);
    }
#pragma unroll
    for (int o = 16; o; o >>= 1) mx = fmaxf(mx, __shfl_xor_sync(0xffffffffu, mx, o));

    float s = 0.f;
#pragma unroll
    for (int u = 0; u < 12; u++) {
        const float p = (vals[u] == -INFINITY) ? 0.f : expf(vals[u] - mx);
        vals[u] = p;
        s += p;
    }
#pragma unroll
    for (int o = 16; o; o >>= 1) s += __shfl_xor_sync(0xffffffffu, s, o);

    const float inv = 1.f / s;
#pragma unroll
    for (int u = 0; u < 12; u++) row[lane + 32 * u] = vals[u] * inv;
}

// ---------------------------------------------------------------------------
// Banded PV: C[(b,i), d] = sum_{l<384} alpha[(b,i), l] * V[(b, i0-128+l), d]
// Block = (dtile, qtile, b) computes 128x128 tile; K-dim = 384.
// ---------------------------------------------------------------------------
__global__ void __launch_bounds__(256)
pv_kernel(const float* __restrict__ E, const float* __restrict__ V,
          float* __restrict__ C)
{
    __shared__ float As[2][8][128];   // [l][m] (alpha, transposed)
    __shared__ float Bs[2][8][128];   // [l][d] (V rows)
    const int b  = blockIdx.z;
    const int i0 = blockIdx.y << 7;
    const int d0 = blockIdx.x << 7;
    const int tid = threadIdx.x;
    const int tx = tid & 15;
    const int ty = tid >> 4;
    const int lr = tid >> 1;          // alpha row
    const int lc = (tid & 1) << 2;    // alpha l-offset
    const int br = tid >> 5;          // V l within stage (0..7)
    const int bc = (tid & 31) << 2;   // V d-offset

    const float* Ap = E + (size_t)(b * NS + i0 + lr) * NWIN + lc;

    float acc[8][8];
#pragma unroll
    for (int i = 0; i < 8; i++)
#pragma unroll
        for (int j = 0; j < 8; j++) acc[i][j] = 0.f;

    float4 apre = *(const float4*)Ap;
    float4 bpre = make_float4(0,0,0,0);
    {
        const int j = i0 - APR + br;
        if (j >= 0 && j < NS)
            bpre = *(const float4*)(V + (size_t)(b * NS + j) * ND + d0 + bc);
    }
    As[0][lc+0][lr] = apre.x; As[0][lc+1][lr] = apre.y;
    As[0][lc+2][lr] = apre.z; As[0][lc+3][lr] = apre.w;
    *(float4*)&Bs[0][br][bc] = bpre;
    __syncthreads();

    int buf = 0;
    const int NT = NWIN / 8;   // 48
    for (int t = 0; t < NT; t++) {
        if (t + 1 < NT) {
            apre = *(const float4*)(Ap + (t + 1) * 8);
            bpre = make_float4(0,0,0,0);
            const int j = i0 - APR + (t + 1) * 8 + br;
            if (j >= 0 && j < NS)
                bpre = *(const float4*)(V + (size_t)(b * NS + j) * ND + d0 + bc);
        }
#pragma unroll
        for (int kk = 0; kk < 8; kk++) {
            float4 a0 = *(const float4*)&As[buf][kk][ty*8];
            float4 a1 = *(const float4*)&As[buf][kk][ty*8+4];
            float4 b0 = *(const float4*)&Bs[buf][kk][tx*8];
            float4 b1 = *(const float4*)&Bs[buf][kk][tx*8+4];
            float av[8] = {a0.x,a0.y,a0.z,a0.w,a1.x,a1.y,a1.z,a1.w};
            float bv[8] = {b0.x,b0.y,b0.z,b0.w,b1.x,b1.y,b1.z,b1.w};
#pragma unroll
            for (int i = 0; i < 8; i++)
#pragma unroll
                for (int j = 0; j < 8; j++)
                    acc[i][j] = fmaf(av[i], bv[j], acc[i][j]);
        }
        if (t + 1 < NT) {
            const int nb = buf ^ 1;
            As[nb][lc+0][lr] = apre.x; As[nb][lc+1][lr] = apre.y;
            As[nb][lc+2][lr] = apre.z; As[nb][lc+3][lr] = apre.w;
            *(float4*)&Bs[nb][br][bc] = bpre;
            __syncthreads();
            buf = nb;
        }
    }

#pragma unroll
    for (int i = 0; i < 8; i++) {
        const size_t off = (size_t)(b * NS + i0 + ty*8 + i) * ND + d0 + tx*8;
        *(float4*)(C + off)     = make_float4(acc[i][0], acc[i][1], acc[i][2], acc[i][3]);
        *(float4*)(C + off + 4) = make_float4(acc[i][4], acc[i][5], acc[i][6], acc[i][7]);
    }
}

// ---------------------------------------------------------------------------
// LayerNorm over D=1024 (one block of 256 threads per row, float4 per thread).
// ---------------------------------------------------------------------------
__global__ void __launch_bounds__(256)
ln_kernel(const float* __restrict__ In, const float* __restrict__ g,
          const float* __restrict__ bt, float* __restrict__ Y)
{
    const int r = blockIdx.x;
    const int tid = threadIdx.x;
    const float4 v = *(const float4*)(In + (size_t)r * ND + tid * 4);
    float s1 = v.x + v.y + v.z + v.w;
    float s2 = v.x*v.x + v.y*v.y + v.z*v.z + v.w*v.w;
    __shared__ float sh1[8], sh2[8];
    const int warp = tid >> 5, lane = tid & 31;
#pragma unroll
    for (int o = 16; o; o >>= 1) {
        s1 += __shfl_xor_sync(0xffffffffu, s1, o);
        s2 += __shfl_xor_sync(0xffffffffu, s2, o);
    }
    if (lane == 0) { sh1[warp] = s1; sh2[warp] = s2; }
    __syncthreads();
    float S1 = 0.f, S2 = 0.f;
#pragma unroll
    for (int w = 0; w < 8; w++) { S1 += sh1[w]; S2 += sh2[w]; }
    const float mu = S1 * (1.f / ND);
    const float var = S2 * (1.f / ND) - mu * mu;
    const float rstd = rsqrtf(var + LN_EPS);
    const float4 gg = *(const float4*)(g + tid * 4);
    const float4 bb = *(const float4*)(bt + tid * 4);
    float4 o;
    o.x = (v.x - mu) * rstd * gg.x + bb.x;
    o.y = (v.y - mu) * rstd * gg.y + bb.y;
    o.z = (v.z - mu) * rstd * gg.z + bb.z;
    o.w = (v.w - mu) * rstd * gg.w + bb.w;
    *(float4*)(Y + (size_t)r * ND + tid * 4) = o;
}

// ---------------------------------------------------------------------------
// Fused LayerNorm + k2 (D->1) + sigmoid. One block per row.
// ---------------------------------------------------------------------------
__global__ void __launch_bounds__(256)
ln_k2_kernel(const float* __restrict__ In, const float* __restrict__ g,
             const float* __restrict__ bt, const float* __restrict__ w2,
             const float* __restrict__ b2, float* __restrict__ Out)
{
    const int r = blockIdx.x;
    const int tid = threadIdx.x;
    const float4 v = *(const float4*)(In + (size_t)r * ND + tid * 4);
    float s1 = v.x + v.y + v.z + v.w;
    float s2 = v.x*v.x + v.y*v.y + v.z*v.z + v.w*v.w;
    __shared__ float sh1[8], sh2[8], sh3[8];
    const int warp = tid >> 5, lane = tid & 31;
#pragma unroll
    for (int o = 16; o; o >>= 1) {
        s1 += __shfl_xor_sync(0xffffffffu, s1, o);
        s2 += __shfl_xor_sync(0xffffffffu, s2, o);
    }
    if (lane == 0) { sh1[warp] = s1; sh2[warp] = s2; }
    __syncthreads();
    float S1 = 0.f, S2 = 0.f;
#pragma unroll
    for (int w = 0; w < 8; w++) { S1 += sh1[w]; S2 += sh2[w]; }
    const float mu = S1 * (1.f / ND);
    const float var = S2 * (1.f / ND) - mu * mu;
    const float rstd = rsqrtf(var + LN_EPS);
    const float4 gg = *(const float4*)(g + tid * 4);
    const float4 bb = *(const float4*)(bt + tid * 4);
    const float4 ww = *(const float4*)(w2 + tid * 4);
    float d = ((v.x - mu) * rstd * gg.x + bb.x) * ww.x
            + ((v.y - mu) * rstd * gg.y + bb.y) * ww.y
            + ((v.z - mu) * rstd * gg.z + bb.z) * ww.z
            + ((v.w - mu) * rstd * gg.w + bb.w) * ww.w;
#pragma unroll
    for (int o = 16; o; o >>= 1) d += __shfl_xor_sync(0xffffffffu, d, o);
    if (lane == 0) sh3[warp] = d;
    __syncthreads();
    if (tid == 0) {
        float D2 = 0.f;
#pragma unroll
        for (int w = 0; w < 8; w++) D2 += sh3[w];
        Out[r] = 1.f / (1.f + expf(-(D2 + b2[0])));
    }
}

// ---------------------------------------------------------------------------
extern "C" void kernel_launch(void* const* d_in, const int* in_sizes, int n_in,
                              void* d_out, int out_size)
{
    const float* x   = (const float*)d_in[0];
    const float* Wq  = (const float*)d_in[1];
    const float* Wk  = (const float*)d_in[2];
    const float* Wv  = (const float*)d_in[3];
    const float* Wo  = (const float*)d_in[4];
    const float* k1w = (const float*)d_in[5];
    const float* k1b = (const float*)d_in[6];
    const float* k2w = (const float*)d_in[7];
    const float* k2b = (const float*)d_in[8];
    const float* lng = (const float*)d_in[9];
    const float* lnb = (const float*)d_in[10];
    float* out = (float*)d_out;

    float *Qd, *Kd, *Vd, *Ed;
    cudaGetSymbolAddress((void**)&Qd, g_Q);
    cudaGetSymbolAddress((void**)&Kd, g_K);
    cudaGetSymbolAddress((void**)&Vd, g_V);
    cudaGetSymbolAddress((void**)&Ed, g_E);

    const dim3 gw(ND / 128, NM / 128);                 // (8, 128)
    sgemm_tn<0><<<gw, 256>>>(x, Wq, nullptr, nullptr, Qd);   // Q
    sgemm_tn<0><<<gw, 256>>>(x, Wk, nullptr, nullptr, Kd);   // K
    sgemm_tn<0><<<gw, 256>>>(x, Wv, nullptr, nullptr, Vd);   // V

    scores_kernel<<<dim3(3, NS / 128, NB), 256>>>(Qd, Kd, Ed);
    softmax_kernel<<<NM / 8, 256>>>(Ed);
    pv_kernel<<<dim3(ND / 128, NS / 128, NB), 256>>>(Ed, Vd, Qd);  // c -> g_Q

    sgemm_tn<2><<<gw, 256>>>(Qd, Wo, nullptr, x, Kd);        // c@Wo^T + x -> g_K
    ln_kernel<<<NM, 256>>>(Kd, lng, lnb, Vd);                // LN1 -> g_V
    sgemm_tn<1><<<gw, 256>>>(Vd, k1w, k1b, nullptr, Qd);     // relu(y@k1^T+b) -> g_Q
    ln_k2_kernel<<<NM, 256>>>(Qd, lng, lnb, k2w, k2b, out);  // LN2 + k2 + sigmoid
}

// round 4
// speedup vs baseline: 2.9875x; 2.9875x over previous
#include <cuda_runtime.h>
#include <math.h>
#include <stdint.h>

#define NB 4
#define NS 4096
#define ND 1024
#define NM (NB*NS)          // 16384 rows
#define NWIN 384
#define APR 128
#define LN_EPS 1e-6f
#define PADK 36             // 32 floats + 4 pad -> conflict-free fragment LDS

// Scratch (static device memory; no allocations anywhere).
__device__ float g_Q[(size_t)NM * ND];
__device__ float g_K[(size_t)NM * ND];
__device__ float g_V[(size_t)NM * ND];
__device__ float g_E[(size_t)NM * NWIN];

__device__ __forceinline__ float to_tf32(float x) {
    float r; asm("cvt.rna.tf32.f32 %0, %1;" : "=f"(r) : "f"(x)); return r;
}
__device__ __forceinline__ void mma_tf32(float* c, const uint32_t* a, const uint32_t* b) {
    asm volatile(
        "mma.sync.aligned.m16n8k8.row.col.f32.tf32.tf32.f32 "
        "{%0,%1,%2,%3}, {%4,%5,%6,%7}, {%8,%9}, {%0,%1,%2,%3};"
        : "+f"(c[0]), "+f"(c[1]), "+f"(c[2]), "+f"(c[3])
        : "r"(a[0]), "r"(a[1]), "r"(a[2]), "r"(a[3]), "r"(b[0]), "r"(b[1]));
}
__device__ __forceinline__ uint32_t fbits(float x) { return __float_as_uint(x); }

#define MMA_SMEM_BYTES (4 * 128 * PADK * 4)   // 2 stages x (A,B) x 128 x PADK floats

// ===========================================================================
// tf32 mma.sync TN GEMM: C[m,n] = sum_k A[m,k] * W[n,k]
// BM=BN=128, BK=32, 8 warps (warp tile 32x64), double-buffered SMEM.
// EPI: 0 = plain, 1 = bias+relu, 2 = +residual
// ===========================================================================
template<int EPI>
__global__ void __launch_bounds__(256, 2)
mma_gemm(const float* __restrict__ A, const float* __restrict__ W,
         const float* __restrict__ bias, const float* __restrict__ res,
         float* __restrict__ C)
{
    extern __shared__ float smem[];
    float* sA = smem;                      // [2][128*PADK]
    float* sB = smem + 2 * 128 * PADK;

    const int m0 = blockIdx.y << 7;
    const int n0 = blockIdx.x << 7;
    const int tid = threadIdx.x;
    const int w = tid >> 5, lane = tid & 31;
    const int wm = (w & 3) * 32, wn = (w >> 2) * 64;
    const int qr = lane >> 2, qc = lane & 3;

    float acc[2][8][4];
#pragma unroll
    for (int i = 0; i < 2; i++)
#pragma unroll
        for (int j = 0; j < 8; j++)
#pragma unroll
            for (int l = 0; l < 4; l++) acc[i][j][l] = 0.f;

    float4 ra[4], rb[4];
    auto ldg_chunk = [&](int t) {
        const float* Ab = A + (size_t)m0 * ND + t * 32;
        const float* Wb = W + (size_t)n0 * ND + t * 32;
#pragma unroll
        for (int i = 0; i < 4; i++) {
            const int idx = tid + i * 256;
            const int row = idx >> 3;
            const int c = (idx & 7) * 4;
            ra[i] = *(const float4*)(Ab + (size_t)row * ND + c);
            rb[i] = *(const float4*)(Wb + (size_t)row * ND + c);
        }
    };
    auto sts_chunk = [&](int s) {
        float* da = sA + s * 128 * PADK;
        float* db = sB + s * 128 * PADK;
#pragma unroll
        for (int i = 0; i < 4; i++) {
            const int idx = tid + i * 256;
            const int off = (idx >> 3) * PADK + (idx & 7) * 4;
            float4 va = ra[i], vb = rb[i];
            va.x = to_tf32(va.x); va.y = to_tf32(va.y);
            va.z = to_tf32(va.z); va.w = to_tf32(va.w);
            vb.x = to_tf32(vb.x); vb.y = to_tf32(vb.y);
            vb.z = to_tf32(vb.z); vb.w = to_tf32(vb.w);
            *(float4*)(da + off) = va;
            *(float4*)(db + off) = vb;
        }
    };
    auto compute = [&](int s) {
        const float* sa = sA + s * 128 * PADK;
        const float* sb = sB + s * 128 * PADK;
#pragma unroll
        for (int ks = 0; ks < 4; ks++) {
            const int k0 = ks * 8;
            uint32_t af[2][4], bf[8][2];
#pragma unroll
            for (int mt = 0; mt < 2; mt++) {
                const float* ba = sa + (wm + mt * 16 + qr) * PADK + k0 + qc;
                af[mt][0] = fbits(ba[0]);
                af[mt][1] = fbits(ba[8 * PADK]);
                af[mt][2] = fbits(ba[4]);
                af[mt][3] = fbits(ba[8 * PADK + 4]);
            }
#pragma unroll
            for (int nt = 0; nt < 8; nt++) {
                const float* bb = sb + (wn + nt * 8 + qr) * PADK + k0 + qc;
                bf[nt][0] = fbits(bb[0]);
                bf[nt][1] = fbits(bb[4]);
            }
#pragma unroll
            for (int mt = 0; mt < 2; mt++)
#pragma unroll
                for (int nt = 0; nt < 8; nt++)
                    mma_tf32(acc[mt][nt], af[mt], bf[nt]);
        }
    };

    const int NT = ND / 32;
    ldg_chunk(0);
    sts_chunk(0);
    __syncthreads();
    for (int t = 0; t < NT; t++) {
        if (t + 1 < NT) ldg_chunk(t + 1);
        compute(t & 1);
        if (t + 1 < NT) {
            sts_chunk((t + 1) & 1);
            __syncthreads();
        }
    }

    // Epilogue
#pragma unroll
    for (int mt = 0; mt < 2; mt++) {
        const int r0 = m0 + wm + mt * 16 + qr;
#pragma unroll
        for (int nt = 0; nt < 8; nt++) {
            const int col = n0 + wn + nt * 8 + qc * 2;
            float2 o0 = make_float2(acc[mt][nt][0], acc[mt][nt][1]);
            float2 o1 = make_float2(acc[mt][nt][2], acc[mt][nt][3]);
            if (EPI == 1) {
                const float b0 = bias[col], b1 = bias[col + 1];
                o0.x = fmaxf(o0.x + b0, 0.f); o0.y = fmaxf(o0.y + b1, 0.f);
                o1.x = fmaxf(o1.x + b0, 0.f); o1.y = fmaxf(o1.y + b1, 0.f);
            }
            if (EPI == 2) {
                const float2 r0v = *(const float2*)(res + (size_t)r0 * ND + col);
                const float2 r1v = *(const float2*)(res + (size_t)(r0 + 8) * ND + col);
                o0.x += r0v.x; o0.y += r0v.y;
                o1.x += r1v.x; o1.y += r1v.y;
            }
            *(float2*)(C + (size_t)r0 * ND + col) = o0;
            *(float2*)(C + (size_t)(r0 + 8) * ND + col) = o1;
        }
    }
}

// ===========================================================================
// Banded scores with tf32 mma.sync: E[(b,i), kt*128+jj] = (Q_i . K_j)/32
// Same 128x128x32 skeleton; B rows come from K with window offset + OOB zero.
// ===========================================================================
__global__ void __launch_bounds__(256, 2)
mma_scores(const float* __restrict__ Q, const float* __restrict__ Km,
           float* __restrict__ E)
{
    extern __shared__ float smem[];
    float* sA = smem;
    float* sB = smem + 2 * 128 * PADK;

    const int b  = blockIdx.z;
    const int i0 = blockIdx.y << 7;
    const int kt = blockIdx.x;
    const int tid = threadIdx.x;
    const int w = tid >> 5, lane = tid & 31;
    const int wm = (w & 3) * 32, wn = (w >> 2) * 64;
    const int qr = lane >> 2, qc = lane & 3;
    const int jbase = i0 - APR + kt * 128;

    float acc[2][8][4];
#pragma unroll
    for (int i = 0; i < 2; i++)
#pragma unroll
        for (int j = 0; j < 8; j++)
#pragma unroll
            for (int l = 0; l < 4; l++) acc[i][j][l] = 0.f;

    float4 ra[4], rb[4];
    auto ldg_chunk = [&](int t) {
        const float* Ab = Q + (size_t)(b * NS + i0) * ND + t * 32;
#pragma unroll
        for (int i = 0; i < 4; i++) {
            const int idx = tid + i * 256;
            const int row = idx >> 3;
            const int c = (idx & 7) * 4;
            ra[i] = *(const float4*)(Ab + (size_t)row * ND + c);
            const int j = jbase + row;
            rb[i] = make_float4(0.f, 0.f, 0.f, 0.f);
            if (j >= 0 && j < NS)
                rb[i] = *(const float4*)(Km + (size_t)(b * NS + j) * ND + t * 32 + c);
        }
    };
    auto sts_chunk = [&](int s) {
        float* da = sA + s * 128 * PADK;
        float* db = sB + s * 128 * PADK;
#pragma unroll
        for (int i = 0; i < 4; i++) {
            const int idx = tid + i * 256;
            const int off = (idx >> 3) * PADK + (idx & 7) * 4;
            float4 va = ra[i], vb = rb[i];
            va.x = to_tf32(va.x); va.y = to_tf32(va.y);
            va.z = to_tf32(va.z); va.w = to_tf32(va.w);
            vb.x = to_tf32(vb.x); vb.y = to_tf32(vb.y);
            vb.z = to_tf32(vb.z); vb.w = to_tf32(vb.w);
            *(float4*)(da + off) = va;
            *(float4*)(db + off) = vb;
        }
    };
    auto compute = [&](int s) {
        const float* sa = sA + s * 128 * PADK;
        const float* sb = sB + s * 128 * PADK;
#pragma unroll
        for (int ks = 0; ks < 4; ks++) {
            const int k0 = ks * 8;
            uint32_t af[2][4], bf[8][2];
#pragma unroll
            for (int mt = 0; mt < 2; mt++) {
                const float* ba = sa + (wm + mt * 16 + qr) * PADK + k0 + qc;
                af[mt][0] = fbits(ba[0]);
                af[mt][1] = fbits(ba[8 * PADK]);
                af[mt][2] = fbits(ba[4]);
                af[mt][3] = fbits(ba[8 * PADK + 4]);
            }
#pragma unroll
            for (int nt = 0; nt < 8; nt++) {
                const float* bb = sb + (wn + nt * 8 + qr) * PADK + k0 + qc;
                bf[nt][0] = fbits(bb[0]);
                bf[nt][1] = fbits(bb[4]);
            }
#pragma unroll
            for (int mt = 0; mt < 2; mt++)
#pragma unroll
                for (int nt = 0; nt < 8; nt++)
                    mma_tf32(acc[mt][nt], af[mt], bf[nt]);
        }
    };

    const int NT = ND / 32;
    ldg_chunk(0);
    sts_chunk(0);
    __syncthreads();
    for (int t = 0; t < NT; t++) {
        if (t + 1 < NT) ldg_chunk(t + 1);
        compute(t & 1);
        if (t + 1 < NT) {
            sts_chunk((t + 1) & 1);
            __syncthreads();
        }
    }

    const float scale = 0.03125f;
#pragma unroll
    for (int mt = 0; mt < 2; mt++) {
        const int r0 = b * NS + i0 + wm + mt * 16 + qr;
#pragma unroll
        for (int nt = 0; nt < 8; nt++) {
            const int col = kt * 128 + wn + nt * 8 + qc * 2;
            *(float2*)(E + (size_t)r0 * NWIN + col) =
                make_float2(acc[mt][nt][0] * scale, acc[mt][nt][1] * scale);
            *(float2*)(E + (size_t)(r0 + 8) * NWIN + col) =
                make_float2(acc[mt][nt][2] * scale, acc[mt][nt][3] * scale);
        }
    }
}

// ===========================================================================
// Banded softmax (unchanged)
// ===========================================================================
__global__ void __launch_bounds__(256)
softmax_kernel(float* __restrict__ E)
{
    const int warp = threadIdx.x >> 5;
    const int lane = threadIdx.x & 31;
    const int r = blockIdx.x * 8 + warp;
    const int i = r & (NS - 1);
    const int i0 = i & ~127;
    const int jbase = i0 - APR;
    float* row = E + (size_t)r * NWIN;

    float vals[12];
    float mx = -INFINITY;
#pragma unroll
    for (int u = 0; u < 12; u++) {
        const int l = lane + 32 * u;
        const int j = jbase + l;
        const float e = row[l];
        const bool ok = (j >= 0) && (j < NS) && (j >= i - APR) && (j <= i + APR)
                        && (j != i) && (e != 0.0f);
        vals[u] = ok ? e : -INFINITY;
        mx = fmaxf(mx, vals[u]);
    }
#pragma unroll
    for (int o = 16; o; o >>= 1) mx = fmaxf(mx, __shfl_xor_sync(0xffffffffu, mx, o));

    float s = 0.f;
#pragma unroll
    for (int u = 0; u < 12; u++) {
        const float p = (vals[u] == -INFINITY) ? 0.f : expf(vals[u] - mx);
        vals[u] = p;
        s += p;
    }
#pragma unroll
    for (int o = 16; o; o >>= 1) s += __shfl_xor_sync(0xffffffffu, s, o);

    const float inv = 1.f / s;
#pragma unroll
    for (int u = 0; u < 12; u++) row[lane + 32 * u] = vals[u] * inv;
}

// ===========================================================================
// Banded PV (FFMA, unchanged)
// ===========================================================================
__global__ void __launch_bounds__(256)
pv_kernel(const float* __restrict__ E, const float* __restrict__ V,
          float* __restrict__ C)
{
    __shared__ float As[2][8][128];
    __shared__ float Bs[2][8][128];
    const int b  = blockIdx.z;
    const int i0 = blockIdx.y << 7;
    const int d0 = blockIdx.x << 7;
    const int tid = threadIdx.x;
    const int tx = tid & 15;
    const int ty = tid >> 4;
    const int lr = tid >> 1;
    const int lc = (tid & 1) << 2;
    const int br = tid >> 5;
    const int bc = (tid & 31) << 2;

    const float* Ap = E + (size_t)(b * NS + i0 + lr) * NWIN + lc;

    float acc[8][8];
#pragma unroll
    for (int i = 0; i < 8; i++)
#pragma unroll
        for (int j = 0; j < 8; j++) acc[i][j] = 0.f;

    float4 apre = *(const float4*)Ap;
    float4 bpre = make_float4(0,0,0,0);
    {
        const int j = i0 - APR + br;
        if (j >= 0 && j < NS)
            bpre = *(const float4*)(V + (size_t)(b * NS + j) * ND + d0 + bc);
    }
    As[0][lc+0][lr] = apre.x; As[0][lc+1][lr] = apre.y;
    As[0][lc+2][lr] = apre.z; As[0][lc+3][lr] = apre.w;
    *(float4*)&Bs[0][br][bc] = bpre;
    __syncthreads();

    int buf = 0;
    const int NT = NWIN / 8;
    for (int t = 0; t < NT; t++) {
        if (t + 1 < NT) {
            apre = *(const float4*)(Ap + (t + 1) * 8);
            bpre = make_float4(0,0,0,0);
            const int j = i0 - APR + (t + 1) * 8 + br;
            if (j >= 0 && j < NS)
                bpre = *(const float4*)(V + (size_t)(b * NS + j) * ND + d0 + bc);
        }
#pragma unroll
        for (int kk = 0; kk < 8; kk++) {
            float4 a0 = *(const float4*)&As[buf][kk][ty*8];
            float4 a1 = *(const float4*)&As[buf][kk][ty*8+4];
            float4 b0 = *(const float4*)&Bs[buf][kk][tx*8];
            float4 b1 = *(const float4*)&Bs[buf][kk][tx*8+4];
            float av[8] = {a0.x,a0.y,a0.z,a0.w,a1.x,a1.y,a1.z,a1.w};
            float bv[8] = {b0.x,b0.y,b0.z,b0.w,b1.x,b1.y,b1.z,b1.w};
#pragma unroll
            for (int i = 0; i < 8; i++)
#pragma unroll
                for (int j = 0; j < 8; j++)
                    acc[i][j] = fmaf(av[i], bv[j], acc[i][j]);
        }
        if (t + 1 < NT) {
            const int nb = buf ^ 1;
            As[nb][lc+0][lr] = apre.x; As[nb][lc+1][lr] = apre.y;
            As[nb][lc+2][lr] = apre.z; As[nb][lc+3][lr] = apre.w;
            *(float4*)&Bs[nb][br][bc] = bpre;
            __syncthreads();
            buf = nb;
        }
    }

#pragma unroll
    for (int i = 0; i < 8; i++) {
        const size_t off = (size_t)(b * NS + i0 + ty*8 + i) * ND + d0 + tx*8;
        *(float4*)(C + off)     = make_float4(acc[i][0], acc[i][1], acc[i][2], acc[i][3]);
        *(float4*)(C + off + 4) = make_float4(acc[i][4], acc[i][5], acc[i][6], acc[i][7]);
    }
}

// ===========================================================================
// LayerNorm + fused LN/k2/sigmoid (unchanged)
// ===========================================================================
__global__ void __launch_bounds__(256)
ln_kernel(const float* __restrict__ In, const float* __restrict__ g,
          const float* __restrict__ bt, float* __restrict__ Y)
{
    const int r = blockIdx.x;
    const int tid = threadIdx.x;
    const float4 v = *(const float4*)(In + (size_t)r * ND + tid * 4);
    float s1 = v.x + v.y + v.z + v.w;
    float s2 = v.x*v.x + v.y*v.y + v.z*v.z + v.w*v.w;
    __shared__ float sh1[8], sh2[8];
    const int warp = tid >> 5, lane = tid & 31;
#pragma unroll
    for (int o = 16; o; o >>= 1) {
        s1 += __shfl_xor_sync(0xffffffffu, s1, o);
        s2 += __shfl_xor_sync(0xffffffffu, s2, o);
    }
    if (lane == 0) { sh1[warp] = s1; sh2[warp] = s2; }
    __syncthreads();
    float S1 = 0.f, S2 = 0.f;
#pragma unroll
    for (int w = 0; w < 8; w++) { S1 += sh1[w]; S2 += sh2[w]; }
    const float mu = S1 * (1.f / ND);
    const float var = S2 * (1.f / ND) - mu * mu;
    const float rstd = rsqrtf(var + LN_EPS);
    const float4 gg = *(const float4*)(g + tid * 4);
    const float4 bb = *(const float4*)(bt + tid * 4);
    float4 o;
    o.x = (v.x - mu) * rstd * gg.x + bb.x;
    o.y = (v.y - mu) * rstd * gg.y + bb.y;
    o.z = (v.z - mu) * rstd * gg.z + bb.z;
    o.w = (v.w - mu) * rstd * gg.w + bb.w;
    *(float4*)(Y + (size_t)r * ND + tid * 4) = o;
}

__global__ void __launch_bounds__(256)
ln_k2_kernel(const float* __restrict__ In, const float* __restrict__ g,
             const float* __restrict__ bt, const float* __restrict__ w2,
             const float* __restrict__ b2, float* __restrict__ Out)
{
    const int r = blockIdx.x;
    const int tid = threadIdx.x;
    const float4 v = *(const float4*)(In + (size_t)r * ND + tid * 4);
    float s1 = v.x + v.y + v.z + v.w;
    float s2 = v.x*v.x + v.y*v.y + v.z*v.z + v.w*v.w;
    __shared__ float sh1[8], sh2[8], sh3[8];
    const int warp = tid >> 5, lane = tid & 31;
#pragma unroll
    for (int o = 16; o; o >>= 1) {
        s1 += __shfl_xor_sync(0xffffffffu, s1, o);
        s2 += __shfl_xor_sync(0xffffffffu, s2, o);
    }
    if (lane == 0) { sh1[warp] = s1; sh2[warp] = s2; }
    __syncthreads();
    float S1 = 0.f, S2 = 0.f;
#pragma unroll
    for (int w = 0; w < 8; w++) { S1 += sh1[w]; S2 += sh2[w]; }
    const float mu = S1 * (1.f / ND);
    const float var = S2 * (1.f / ND) - mu * mu;
    const float rstd = rsqrtf(var + LN_EPS);
    const float4 gg = *(const float4*)(g + tid * 4);
    const float4 bb = *(const float4*)(bt + tid * 4);
    const float4 ww = *(const float4*)(w2 + tid * 4);
    float d = ((v.x - mu) * rstd * gg.x + bb.x) * ww.x
            + ((v.y - mu) * rstd * gg.y + bb.y) * ww.y
            + ((v.z - mu) * rstd * gg.z + bb.z) * ww.z
            + ((v.w - mu) * rstd * gg.w + bb.w) * ww.w;
#pragma unroll
    for (int o = 16; o; o >>= 1) d += __shfl_xor_sync(0xffffffffu, d, o);
    if (lane == 0) sh3[warp] = d;
    __syncthreads();
    if (tid == 0) {
        float D2 = 0.f;
#pragma unroll
        for (int w = 0; w < 8; w++) D2 += sh3[w];
        Out[r] = 1.f / (1.f + expf(-(D2 + b2[0])));
    }
}

// ===========================================================================
extern "C" void kernel_launch(void* const* d_in, const int* in_sizes, int n_in,
                              void* d_out, int out_size)
{
    const float* x   = (const float*)d_in[0];
    const float* Wq  = (const float*)d_in[1];
    const float* Wk  = (const float*)d_in[2];
    const float* Wv  = (const float*)d_in[3];
    const float* Wo  = (const float*)d_in[4];
    const float* k1w = (const float*)d_in[5];
    const float* k1b = (const float*)d_in[6];
    const float* k2w = (const float*)d_in[7];
    const float* k2b = (const float*)d_in[8];
    const float* lng = (const float*)d_in[9];
    const float* lnb = (const float*)d_in[10];
    float* out = (float*)d_out;

    float *Qd, *Kd, *Vd, *Ed;
    cudaGetSymbolAddress((void**)&Qd, g_Q);
    cudaGetSymbolAddress((void**)&Kd, g_K);
    cudaGetSymbolAddress((void**)&Vd, g_V);
    cudaGetSymbolAddress((void**)&Ed, g_E);

    cudaFuncSetAttribute(mma_gemm<0>, cudaFuncAttributeMaxDynamicSharedMemorySize, MMA_SMEM_BYTES);
    cudaFuncSetAttribute(mma_gemm<1>, cudaFuncAttributeMaxDynamicSharedMemorySize, MMA_SMEM_BYTES);
    cudaFuncSetAttribute(mma_gemm<2>, cudaFuncAttributeMaxDynamicSharedMemorySize, MMA_SMEM_BYTES);
    cudaFuncSetAttribute(mma_scores,  cudaFuncAttributeMaxDynamicSharedMemorySize, MMA_SMEM_BYTES);

    const dim3 gw(ND / 128, NM / 128);   // (8, 128)
    mma_gemm<0><<<gw, 256, MMA_SMEM_BYTES>>>(x, Wq, nullptr, nullptr, Qd);  // Q
    mma_gemm<0><<<gw, 256, MMA_SMEM_BYTES>>>(x, Wk, nullptr, nullptr, Kd);  // K
    mma_gemm<0><<<gw, 256, MMA_SMEM_BYTES>>>(x, Wv, nullptr, nullptr, Vd);  // V

    mma_scores<<<dim3(3, NS / 128, NB), 256, MMA_SMEM_BYTES>>>(Qd, Kd, Ed);
    softmax_kernel<<<NM / 8, 256>>>(Ed);
    pv_kernel<<<dim3(ND / 128, NS / 128, NB), 256>>>(Ed, Vd, Qd);           // c -> g_Q

    mma_gemm<2><<<gw, 256, MMA_SMEM_BYTES>>>(Qd, Wo, nullptr, x, Kd);       // c@Wo^T + x
    ln_kernel<<<NM, 256>>>(Kd, lng, lnb, Vd);                               // LN1
    mma_gemm<1><<<gw, 256, MMA_SMEM_BYTES>>>(Vd, k1w, k1b, nullptr, Qd);    // relu(y@k1^T+b)
    ln_k2_kernel<<<NM, 256>>>(Qd, lng, lnb, k2w, k2b, out);                 // LN2 + k2 + sigmoid
}

// round 9
// speedup vs baseline: 3.6276x; 1.2142x over previous
#include <cuda_runtime.h>
#include <math.h>
#include <stdint.h>

#define NB 4
#define NS 4096
#define ND 1024
#define NM (NB*NS)          // 16384 rows
#define NWIN 384
#define APR 128
#define LN_EPS 1e-6f
#define PADK 36

// Scratch (static device memory; no allocations anywhere).
__device__ float g_Q[(size_t)NM * ND];
__device__ float g_K[(size_t)NM * ND];
__device__ float g_V[(size_t)NM * ND];
__device__ float g_E[(size_t)NM * NWIN];
__device__ float g_XT[(size_t)NM * ND];        // tf32-rounded x
__device__ float g_WT[(size_t)5 * ND * ND];    // tf32-rounded Wq,Wk,Wv,Wo,k1w

// ---------------------------------------------------------------------------
__device__ __forceinline__ float to_tf32(float x) {
    float r; asm("cvt.rna.tf32.f32 %0, %1;" : "=f"(r) : "f"(x)); return r;
}
__device__ __forceinline__ uint32_t fbits(float x) { return __float_as_uint(x); }
__device__ __forceinline__ uint32_t smem_u32(const void* p) {
    uint32_t a;
    asm("{ .reg .u64 t; cvta.to.shared.u64 t, %1; cvt.u32.u64 %0, t; }"
        : "=r"(a) : "l"(p));
    return a;
}
__device__ __forceinline__ void mma_tf32(float* c, const uint32_t* a, const uint32_t* b) {
    asm volatile(
        "mma.sync.aligned.m16n8k8.row.col.f32.tf32.tf32.f32 "
        "{%0,%1,%2,%3}, {%4,%5,%6,%7}, {%8,%9}, {%0,%1,%2,%3};"
        : "+f"(c[0]), "+f"(c[1]), "+f"(c[2]), "+f"(c[3])
        : "r"(a[0]), "r"(a[1]), "r"(a[2]), "r"(a[3]), "r"(b[0]), "r"(b[1]));
}
__device__ __forceinline__ void cp16(uint32_t dst, const void* src) {
    asm volatile("cp.async.cg.shared.global [%0], [%1], 16;"
                 :: "r"(dst), "l"(src) : "memory");
}
__device__ __forceinline__ void cp16z(uint32_t dst, const void* src, uint32_t nbytes) {
    asm volatile("cp.async.cg.shared.global [%0], [%1], 16, %2;"
                 :: "r"(dst), "l"(src), "r"(nbytes) : "memory");
}
__device__ __forceinline__ void cp_commit() {
    asm volatile("cp.async.commit_group;" ::: "memory");
}
__device__ __forceinline__ void cp_wait0() {
    asm volatile("cp.async.wait_group 0;" ::: "memory");
}

// Shared inner compute: one 128x128x32 chunk with tf32 mma.sync.
__device__ __forceinline__ void mma_compute_chunk(
    const float* __restrict__ sa, const float* __restrict__ sb,
    float (&acc)[2][8][4], int wm, int wn, int qr, int qc)
{
#pragma unroll
    for (int ks = 0; ks < 4; ks++) {
        const int k0 = ks * 8;
        uint32_t af[2][4], bf[8][2];
#pragma unroll
        for (int mt = 0; mt < 2; mt++) {
            const float* ba = sa + (wm + mt * 16 + qr) * PADK + k0 + qc;
            af[mt][0] = fbits(ba[0]);
            af[mt][1] = fbits(ba[8 * PADK]);
            af[mt][2] = fbits(ba[4]);
            af[mt][3] = fbits(ba[8 * PADK + 4]);
        }
#pragma unroll
        for (int nt = 0; nt < 8; nt++) {
            const float* bb = sb + (wn + nt * 8 + qr) * PADK + k0 + qc;
            bf[nt][0] = fbits(bb[0]);
            bf[nt][1] = fbits(bb[4]);
        }
#pragma unroll
        for (int mt = 0; mt < 2; mt++)
#pragma unroll
            for (int nt = 0; nt < 8; nt++)
                mma_tf32(acc[mt][nt], af[mt], bf[nt]);
    }
}

// ---------------------------------------------------------------------------
// tf32 round-copy kernels (one-time prep of GEMM operands).
// ---------------------------------------------------------------------------
__global__ void __launch_bounds__(256)
round_copy(const float* __restrict__ src, float* __restrict__ dst)
{
    const size_t i = ((size_t)blockIdx.x * 256 + threadIdx.x) * 4;
    float4 v = *(const float4*)(src + i);
    v.x = to_tf32(v.x); v.y = to_tf32(v.y);
    v.z = to_tf32(v.z); v.w = to_tf32(v.w);
    *(float4*)(dst + i) = v;
}

// ===========================================================================
// tf32 mma.sync TN GEMM with cp.async double-buffered pipeline.
// C[m,n] = sum_k A[m,k] * W[n,k]; A, W already tf32-rounded in gmem.
// EPI: 0 = plain, 1 = bias+relu, 2 = +residual.  ROUND: tf32-round output.
// ===========================================================================
#define STG_FLOATS (128 * PADK)
#define GEMM2_SMEM (4 * STG_FLOATS * 4)

template<int EPI, int ROUND>
__global__ void __launch_bounds__(256, 2)
mma_gemm2(const float* __restrict__ A, const float* __restrict__ W,
          const float* __restrict__ bias, const float* __restrict__ res,
          float* __restrict__ C)
{
    extern __shared__ float smem[];
    const uint32_t sb32 = smem_u32(smem);

    const int m0 = blockIdx.y << 7;
    const int n0 = blockIdx.x << 7;
    const int tid = threadIdx.x;
    const int w = tid >> 5, lane = tid & 31;
    const int wm = (w & 3) * 32, wn = (w >> 2) * 64;
    const int qr = lane >> 2, qc = lane & 3;

    float acc[2][8][4];
#pragma unroll
    for (int i = 0; i < 2; i++)
#pragma unroll
        for (int j = 0; j < 8; j++)
#pragma unroll
            for (int l = 0; l < 4; l++) acc[i][j][l] = 0.f;

    auto cp_chunk = [&](int t, int s) {
        const uint32_t dA = sb32 + (uint32_t)s * STG_FLOATS * 4;
        const uint32_t dB = sb32 + (uint32_t)(2 + s) * STG_FLOATS * 4;
        const float* Ab = A + (size_t)m0 * ND + t * 32;
        const float* Wb = W + (size_t)n0 * ND + t * 32;
#pragma unroll
        for (int i = 0; i < 4; i++) {
            const int idx = tid + i * 256;
            const int row = idx >> 3;
            const int seg = idx & 7;
            const uint32_t off = (uint32_t)(row * PADK + seg * 4) * 4;
            cp16(dA + off, Ab + (size_t)row * ND + seg * 4);
            cp16(dB + off, Wb + (size_t)row * ND + seg * 4);
        }
        cp_commit();
    };

    const int NT = ND / 32;
    cp_chunk(0, 0);
    for (int t = 0; t < NT; t++) {
        cp_wait0();
        __syncthreads();
        if (t + 1 < NT) cp_chunk(t + 1, (t + 1) & 1);
        const int s = t & 1;
        mma_compute_chunk(smem + s * STG_FLOATS, smem + (2 + s) * STG_FLOATS,
                          acc, wm, wn, qr, qc);
    }

    // Epilogue
#pragma unroll
    for (int mt = 0; mt < 2; mt++) {
        const int r0 = m0 + wm + mt * 16 + qr;
#pragma unroll
        for (int nt = 0; nt < 8; nt++) {
            const int col = n0 + wn + nt * 8 + qc * 2;
            float2 o0 = make_float2(acc[mt][nt][0], acc[mt][nt][1]);
            float2 o1 = make_float2(acc[mt][nt][2], acc[mt][nt][3]);
            if (EPI == 1) {
                const float b0 = bias[col], b1 = bias[col + 1];
                o0.x = fmaxf(o0.x + b0, 0.f); o0.y = fmaxf(o0.y + b1, 0.f);
                o1.x = fmaxf(o1.x + b0, 0.f); o1.y = fmaxf(o1.y + b1, 0.f);
            }
            if (EPI == 2) {
                const float2 r0v = *(const float2*)(res + (size_t)r0 * ND + col);
                const float2 r1v = *(const float2*)(res + (size_t)(r0 + 8) * ND + col);
                o0.x += r0v.x; o0.y += r0v.y;
                o1.x += r1v.x; o1.y += r1v.y;
            }
            if (ROUND) {
                o0.x = to_tf32(o0.x); o0.y = to_tf32(o0.y);
                o1.x = to_tf32(o1.x); o1.y = to_tf32(o1.y);
            }
            *(float2*)(C + (size_t)r0 * ND + col) = o0;
            *(float2*)(C + (size_t)(r0 + 8) * ND + col) = o1;
        }
    }
}

// ===========================================================================
// Banded scores with cp.async: E = (Q . K^T) / 32 over the 384 window.
// ===========================================================================
__global__ void __launch_bounds__(256, 2)
mma_scores2(const float* __restrict__ Q, const float* __restrict__ Km,
            float* __restrict__ E)
{
    extern __shared__ float smem[];
    const uint32_t sb32 = smem_u32(smem);

    const int b  = blockIdx.z;
    const int i0 = blockIdx.y << 7;
    const int kt = blockIdx.x;
    const int tid = threadIdx.x;
    const int w = tid >> 5, lane = tid & 31;
    const int wm = (w & 3) * 32, wn = (w >> 2) * 64;
    const int qr = lane >> 2, qc = lane & 3;
    const int jbase = i0 - APR + kt * 128;

    float acc[2][8][4];
#pragma unroll
    for (int i = 0; i < 2; i++)
#pragma unroll
        for (int j = 0; j < 8; j++)
#pragma unroll
            for (int l = 0; l < 4; l++) acc[i][j][l] = 0.f;

    auto cp_chunk = [&](int t, int s) {
        const uint32_t dA = sb32 + (uint32_t)s * STG_FLOATS * 4;
        const uint32_t dB = sb32 + (uint32_t)(2 + s) * STG_FLOATS * 4;
        const float* Ab = Q + (size_t)(b * NS + i0) * ND + t * 32;
#pragma unroll
        for (int i = 0; i < 4; i++) {
            const int idx = tid + i * 256;
            const int row = idx >> 3;
            const int seg = idx & 7;
            const uint32_t off = (uint32_t)(row * PADK + seg * 4) * 4;
            cp16(dA + off, Ab + (size_t)row * ND + seg * 4);
            const int j = jbase + row;
            const bool ok = (j >= 0) && (j < NS);
            const int jc = ok ? j : 0;
            cp16z(dB + off, Km + (size_t)(b * NS + jc) * ND + t * 32 + seg * 4,
                  ok ? 16u : 0u);
        }
        cp_commit();
    };

    const int NT = ND / 32;
    cp_chunk(0, 0);
    for (int t = 0; t < NT; t++) {
        cp_wait0();
        __syncthreads();
        if (t + 1 < NT) cp_chunk(t + 1, (t + 1) & 1);
        const int s = t & 1;
        mma_compute_chunk(smem + s * STG_FLOATS, smem + (2 + s) * STG_FLOATS,
                          acc, wm, wn, qr, qc);
    }

    const float scale = 0.03125f;
#pragma unroll
    for (int mt = 0; mt < 2; mt++) {
        const int r0 = b * NS + i0 + wm + mt * 16 + qr;
#pragma unroll
        for (int nt = 0; nt < 8; nt++) {
            const int col = kt * 128 + wn + nt * 8 + qc * 2;
            *(float2*)(E + (size_t)r0 * NWIN + col) =
                make_float2(acc[mt][nt][0] * scale, acc[mt][nt][1] * scale);
            *(float2*)(E + (size_t)(r0 + 8) * NWIN + col) =
                make_float2(acc[mt][nt][2] * scale, acc[mt][nt][3] * scale);
        }
    }
}

// ===========================================================================
// Banded PV with tf32 mma: C[i,d] = sum_l alpha[i,l] * V[jbase+l, d]
// V staged coalesced into sVt[l][d], transposed in SMEM to sB[d][l].
// ===========================================================================
#define PV_A_FLOATS (128 * PADK)       // 4608 per stage
#define PV_VT_FLOATS (32 * 132)        // 4224 per stage
#define PV_VT_OFF (2 * PV_A_FLOATS)
#define PV_B_OFF (PV_VT_OFF + 2 * PV_VT_FLOATS)
#define PV_SMEM ((PV_B_OFF + 128 * PADK) * 4)

__global__ void __launch_bounds__(256, 2)
pv_mma(const float* __restrict__ E, const float* __restrict__ V,
       float* __restrict__ C)
{
    extern __shared__ float smem[];
    const uint32_t sb32 = smem_u32(smem);

    const int b  = blockIdx.z;
    const int i0 = blockIdx.y << 7;
    const int d0 = blockIdx.x << 7;
    const int tid = threadIdx.x;
    const int w = tid >> 5, lane = tid & 31;
    const int wm = (w & 3) * 32, wn = (w >> 2) * 64;
    const int qr = lane >> 2, qc = lane & 3;
    const int jbase = i0 - APR;

    float acc[2][8][4];
#pragma unroll
    for (int i = 0; i < 2; i++)
#pragma unroll
        for (int j = 0; j < 8; j++)
#pragma unroll
            for (int l = 0; l < 4; l++) acc[i][j][l] = 0.f;

    auto cp_chunk = [&](int t, int s) {
        // alpha rows: 128 x 32
        const uint32_t dA = sb32 + (uint32_t)s * PV_A_FLOATS * 4;
        const float* Ab = E + (size_t)(b * NS + i0) * NWIN + t * 32;
#pragma unroll
        for (int i = 0; i < 4; i++) {
            const int idx = tid + i * 256;
            const int row = idx >> 3;
            const int seg = idx & 7;
            cp16(dA + (uint32_t)(row * PADK + seg * 4) * 4,
                 Ab + (size_t)row * NWIN + seg * 4);
        }
        // V rows: 32 x 128 coalesced into sVt[l][d]
        const uint32_t dV = sb32 + (uint32_t)(PV_VT_OFF + s * PV_VT_FLOATS) * 4;
#pragma unroll
        for (int i = 0; i < 4; i++) {
            const int idx = tid + i * 256;
            const int lrow = idx >> 5;
            const int dseg = idx & 31;
            const int j = jbase + t * 32 + lrow;
            const bool ok = (j >= 0) && (j < NS);
            const int jc = ok ? j : 0;
            cp16z(dV + (uint32_t)(lrow * 132 + dseg * 4) * 4,
                  V + (size_t)(b * NS + jc) * ND + d0 + dseg * 4,
                  ok ? 16u : 0u);
        }
        cp_commit();
    };

    const int NT = NWIN / 32;   // 12
    cp_chunk(0, 0);
    for (int t = 0; t < NT; t++) {
        cp_wait0();
        __syncthreads();
        // transpose sVt[t&1] -> sB (single buffer)
        {
            const float* sv = smem + PV_VT_OFF + (t & 1) * PV_VT_FLOATS;
            float* sB = smem + PV_B_OFF;
            const int d = tid >> 1;
            const int l0 = (tid & 1) * 16;
#pragma unroll
            for (int s16 = 0; s16 < 16; s16++) {
                const int l = l0 + s16;
                sB[d * PADK + l] = sv[l * 132 + d];
            }
        }
        if (t + 1 < NT) cp_chunk(t + 1, (t + 1) & 1);
        __syncthreads();
        mma_compute_chunk(smem + (t & 1) * PV_A_FLOATS, smem + PV_B_OFF,
                          acc, wm, wn, qr, qc);
    }

    // Epilogue: rounded (feeds Wo GEMM)
#pragma unroll
    for (int mt = 0; mt < 2; mt++) {
        const int r0 = b * NS + i0 + wm + mt * 16 + qr;
#pragma unroll
        for (int nt = 0; nt < 8; nt++) {
            const int col = d0 + wn + nt * 8 + qc * 2;
            float2 o0 = make_float2(to_tf32(acc[mt][nt][0]), to_tf32(acc[mt][nt][1]));
            float2 o1 = make_float2(to_tf32(acc[mt][nt][2]), to_tf32(acc[mt][nt][3]));
            *(float2*)(C + (size_t)r0 * ND + col) = o0;
            *(float2*)(C + (size_t)(r0 + 8) * ND + col) = o1;
        }
    }
}

// ===========================================================================
// Banded softmax; output tf32-rounded (feeds pv_mma).
// ===========================================================================
__global__ void __launch_bounds__(256)
softmax_kernel(float* __restrict__ E)
{
    const int warp = threadIdx.x >> 5;
    const int lane = threadIdx.x & 31;
    const int r = blockIdx.x * 8 + warp;
    const int i = r & (NS - 1);
    const int i0 = i & ~127;
    const int jbase = i0 - APR;
    float* row = E + (size_t)r * NWIN;

    float vals[12];
    float mx = -INFINITY;
#pragma unroll
    for (int u = 0; u < 12; u++) {
        const int l = lane + 32 * u;
        const int j = jbase + l;
        const float e = row[l];
        const bool ok = (j >= 0) && (j < NS) && (j >= i - APR) && (j <= i + APR)
                        && (j != i) && (e != 0.0f);
        vals[u] = ok ? e : -INFINITY;
        mx = fmaxf(mx, vals[u]);
    }
#pragma unroll
    for (int o = 16; o; o >>= 1) mx = fmaxf(mx, __shfl_xor_sync(0xffffffffu, mx, o));

    float s = 0.f;
#pragma unroll
    for (int u = 0; u < 12; u++) {
        const float p = (vals[u] == -INFINITY) ? 0.f : expf(vals[u] - mx);
        vals[u] = p;
        s += p;
    }
#pragma unroll
    for (int o = 16; o; o >>= 1) s += __shfl_xor_sync(0xffffffffu, s, o);

    const float inv = 1.f / s;
#pragma unroll
    for (int u = 0; u < 12; u++) row[lane + 32 * u] = to_tf32(vals[u] * inv);
}

// ===========================================================================
// LayerNorm; ROUND=1 rounds output to tf32 (feeds a GEMM).
// ===========================================================================
template<int ROUND>
__global__ void __launch_bounds__(256)
ln_kernel(const float* __restrict__ In, const float* __restrict__ g,
          const float* __restrict__ bt, float* __restrict__ Y)
{
    const int r = blockIdx.x;
    const int tid = threadIdx.x;
    const float4 v = *(const float4*)(In + (size_t)r * ND + tid * 4);
    float s1 = v.x + v.y + v.z + v.w;
    float s2 = v.x*v.x + v.y*v.y + v.z*v.z + v.w*v.w;
    __shared__ float sh1[8], sh2[8];
    const int warp = tid >> 5, lane = tid & 31;
#pragma unroll
    for (int o = 16; o; o >>= 1) {
        s1 += __shfl_xor_sync(0xffffffffu, s1, o);
        s2 += __shfl_xor_sync(0xffffffffu, s2, o);
    }
    if (lane == 0) { sh1[warp] = s1; sh2[warp] = s2; }
    __syncthreads();
    float S1 = 0.f, S2 = 0.f;
#pragma unroll
    for (int w = 0; w < 8; w++) { S1 += sh1[w]; S2 += sh2[w]; }
    const float mu = S1 * (1.f / ND);
    const float var = S2 * (1.f / ND) - mu * mu;
    const float rstd = rsqrtf(var + LN_EPS);
    const float4 gg = *(const float4*)(g + tid * 4);
    const float4 bb = *(const float4*)(bt + tid * 4);
    float4 o;
    o.x = (v.x - mu) * rstd * gg.x + bb.x;
    o.y = (v.y - mu) * rstd * gg.y + bb.y;
    o.z = (v.z - mu) * rstd * gg.z + bb.z;
    o.w = (v.w - mu) * rstd * gg.w + bb.w;
    if (ROUND) {
        o.x = to_tf32(o.x); o.y = to_tf32(o.y);
        o.z = to_tf32(o.z); o.w = to_tf32(o.w);
    }
    *(float4*)(Y + (size_t)r * ND + tid * 4) = o;
}

__global__ void __launch_bounds__(256)
ln_k2_kernel(const float* __restrict__ In, const float* __restrict__ g,
             const float* __restrict__ bt, const float* __restrict__ w2,
             const float* __restrict__ b2, float* __restrict__ Out)
{
    const int r = blockIdx.x;
    const int tid = threadIdx.x;
    const float4 v = *(const float4*)(In + (size_t)r * ND + tid * 4);
    float s1 = v.x + v.y + v.z + v.w;
    float s2 = v.x*v.x + v.y*v.y + v.z*v.z + v.w*v.w;
    __shared__ float sh1[8], sh2[8], sh3[8];
    const int warp = tid >> 5, lane = tid & 31;
#pragma unroll
    for (int o = 16; o; o >>= 1) {
        s1 += __shfl_xor_sync(0xffffffffu, s1, o);
        s2 += __shfl_xor_sync(0xffffffffu, s2, o);
    }
    if (lane == 0) { sh1[warp] = s1; sh2[warp] = s2; }
    __syncthreads();
    float S1 = 0.f, S2 = 0.f;
#pragma unroll
    for (int w = 0; w < 8; w++) { S1 += sh1[w]; S2 += sh2[w]; }
    const float mu = S1 * (1.f / ND);
    const float var = S2 * (1.f / ND) - mu * mu;
    const float rstd = rsqrtf(var + LN_EPS);
    const float4 gg = *(const float4*)(g + tid * 4);
    const float4 bb = *(const float4*)(bt + tid * 4);
    const float4 ww = *(const float4*)(w2 + tid * 4);
    float d = ((v.x - mu) * rstd * gg.x + bb.x) * ww.x
            + ((v.y - mu) * rstd * gg.y + bb.y) * ww.y
            + ((v.z - mu) * rstd * gg.z + bb.z) * ww.z
            + ((v.w - mu) * rstd * gg.w + bb.w) * ww.w;
#pragma unroll
    for (int o = 16; o; o >>= 1) d += __shfl_xor_sync(0xffffffffu, d, o);
    if (lane == 0) sh3[warp] = d;
    __syncthreads();
    if (tid == 0) {
        float D2 = 0.f;
#pragma unroll
        for (int w = 0; w < 8; w++) D2 += sh3[w];
        Out[r] = 1.f / (1.f + expf(-(D2 + b2[0])));
    }
}

// ===========================================================================
extern "C" void kernel_launch(void* const* d_in, const int* in_sizes, int n_in,
                              void* d_out, int out_size)
{
    const float* x   = (const float*)d_in[0];
    const float* Wq  = (const float*)d_in[1];
    const float* Wk  = (const float*)d_in[2];
    const float* Wv  = (const float*)d_in[3];
    const float* Wo  = (const float*)d_in[4];
    const float* k1w = (const float*)d_in[5];
    const float* k1b = (const float*)d_in[6];
    const float* k2w = (const float*)d_in[7];
    const float* k2b = (const float*)d_in[8];
    const float* lng = (const float*)d_in[9];
    const float* lnb = (const float*)d_in[10];
    float* out = (float*)d_out;

    float *Qd, *Kd, *Vd, *Ed, *XT, *WT;
    cudaGetSymbolAddress((void**)&Qd, g_Q);
    cudaGetSymbolAddress((void**)&Kd, g_K);
    cudaGetSymbolAddress((void**)&Vd, g_V);
    cudaGetSymbolAddress((void**)&Ed, g_E);
    cudaGetSymbolAddress((void**)&XT, g_XT);
    cudaGetSymbolAddress((void**)&WT, g_WT);

    cudaFuncSetAttribute(mma_gemm2<0,1>, cudaFuncAttributeMaxDynamicSharedMemorySize, GEMM2_SMEM);
    cudaFuncSetAttribute(mma_gemm2<1,0>, cudaFuncAttributeMaxDynamicSharedMemorySize, GEMM2_SMEM);
    cudaFuncSetAttribute(mma_gemm2<2,0>, cudaFuncAttributeMaxDynamicSharedMemorySize, GEMM2_SMEM);
    cudaFuncSetAttribute(mma_scores2,   cudaFuncAttributeMaxDynamicSharedMemorySize, GEMM2_SMEM);
    cudaFuncSetAttribute(pv_mma,        cudaFuncAttributeMaxDynamicSharedMemorySize, PV_SMEM);

    // Prep: tf32-round GEMM operands.
    round_copy<<<(NM * ND) / 1024, 256>>>(x, XT);
    round_copy<<<(ND * ND) / 1024, 256>>>(Wq,  WT + 0 * (size_t)ND * ND);
    round_copy<<<(ND * ND) / 1024, 256>>>(Wk,  WT + 1 * (size_t)ND * ND);
    round_copy<<<(ND * ND) / 1024, 256>>>(Wv,  WT + 2 * (size_t)ND * ND);
    round_copy<<<(ND * ND) / 1024, 256>>>(Wo,  WT + 3 * (size_t)ND * ND);
    round_copy<<<(ND * ND) / 1024, 256>>>(k1w, WT + 4 * (size_t)ND * ND);

    const dim3 gw(ND / 128, NM / 128);   // (8, 128)
    mma_gemm2<0,1><<<gw, 256, GEMM2_SMEM>>>(XT, WT + 0*(size_t)ND*ND, nullptr, nullptr, Qd);
    mma_gemm2<0,1><<<gw, 256, GEMM2_SMEM>>>(XT, WT + 1*(size_t)ND*ND, nullptr, nullptr, Kd);
    mma_gemm2<0,1><<<gw, 256, GEMM2_SMEM>>>(XT, WT + 2*(size_t)ND*ND, nullptr, nullptr, Vd);

    mma_scores2<<<dim3(3, NS / 128, NB), 256, GEMM2_SMEM>>>(Qd, Kd, Ed);
    softmax_kernel<<<NM / 8, 256>>>(Ed);
    pv_mma<<<dim3(ND / 128, NS / 128, NB), 256, PV_SMEM>>>(Ed, Vd, Qd);   // c -> g_Q

    mma_gemm2<2,0><<<gw, 256, GEMM2_SMEM>>>(Qd, WT + 3*(size_t)ND*ND, nullptr, x, Kd);
    ln_kernel<1><<<NM, 256>>>(Kd, lng, lnb, Vd);                          // y (tf32) -> g_V
    mma_gemm2<1,0><<<gw, 256, GEMM2_SMEM>>>(Vd, WT + 4*(size_t)ND*ND, k1b, nullptr, Qd);
    ln_k2_kernel<<<NM, 256>>>(Qd, lng, lnb, k2w, k2b, out);
}